// round 9
// baseline (speedup 1.0000x reference)
#include <cuda_runtime.h>

// QSP expectation via per-block table + cubic interpolation.
//
// g(theta) = Re(e^{i phi0} P00) = sum_{j<=27} A_j cos(2j th) + B_j sin(2j th)
//   -> pi-periodic, band-limited (54). Per block (one per SM):
//   1) 54-step chain split into two 27-step halves (rows x cols, 128 threads)
//      at 64 samples -> exact 64-pt DFT -> A_j, B_j (packed float2 (A,B)).
//   2) 1024-entry table of g over [0,pi): ONE grid point per thread, scalar
//      Clenshaw, 3-deep float2 coefficient prefetch.
//   3) float4 stencil table; eval: range-reduce, one LDS.128, cubic Lagrange.

#define NSTEP 54
#define NHARM 27
#define NSAMP 64
#define TSIZE 1024

__global__ void __launch_bounds__(1024, 1)
qsp_fused(const float4* __restrict__ x4,
          const float*  __restrict__ phis,
          const float4* __restrict__ a4,
          const float*  __restrict__ bias,
          float4* __restrict__ out4,
          int nq)                       // nq = n/4
{
    __shared__ float pc[NSTEP], ps[NSTEP];
    __shared__ float s0cs[2];
    __shared__ float lh[64 * 4], rh[64 * 4];      // half-chain results
    __shared__ float gs[NSAMP];                   // g at 64 chain samples
    __shared__ float tab[NSAMP];                  // sinpi table for DFT
    __shared__ __align__(8)  float2 sAB[NHARM + 1];   // (A_k, B_k)
    __shared__ __align__(16) float  g[TSIZE];     // g over one period
    __shared__ __align__(16) float4 t4[TSIZE];    // stencil g[i-1..i+2]

    const int t = threadIdx.x;
    const int T = blockIdx.x * blockDim.x + t;
    const bool act = (T < nq);

    // ---- eval-path global loads issued FIRST ----
    float4 xv = make_float4(0.f, 0.f, 0.f, 0.f);
    float4 av = xv;
    if (act) { xv = x4[T]; av = a4[T]; }
    const float bb = bias[0];

    // ---- phase setup ----
    if (t < NSTEP) {
        float sp, cp; sincosf(phis[t + 1], &sp, &cp);   // accurate, one-time
        pc[t] = cp; ps[t] = sp;
    }
    if (t == 192) {
        float sp, cp; sincosf(phis[0], &sp, &cp);
        s0cs[0] = cp; s0cs[1] = sp;
    }
    if (t >= 128 && t < 128 + NSAMP) {
        const int i = t - 128;
        tab[i] = sinpif((float)i * (1.0f / 32.0f));     // sin(pi*i/32)
    }
    __syncthreads();

    // ---- chain split: threads 0-63 left rows, 64-127 right (transposed) ----
    if (t < 128) {
        const int i = t & 63;
        float s, c; sincospif((float)i * (1.0f / 64.0f), &s, &c);
        float x0, y0, x1, y1;
        if (t < 64) {
            // row r = e0^T * M_1..M_27, iterate r <- r*(W S)
            x0 = 1.f; y0 = 0.f; x1 = 0.f; y1 = 0.f;
            #pragma unroll
            for (int k = 0; k < NHARM; ++k) {
                const float ec = pc[k], es = ps[k];
                const float ux = c * x0 - s * y1, uy = c * y0 + s * x1;
                const float vx = c * x1 - s * y0, vy = c * y1 + s * x0;
                x0 = ec * ux - es * uy; y0 = es * ux + ec * uy;
                x1 = ec * vx + es * vy; y1 = ec * vy - es * vx;
            }
            lh[i*4+0] = x0; lh[i*4+1] = y0; lh[i*4+2] = x1; lh[i*4+3] = y1;
        } else {
            // col v = M_28..M_54 * e0 via transpose rows: r <- r*(S_k W), k=53..27
            x0 = 1.f; y0 = 0.f; x1 = 0.f; y1 = 0.f;
            #pragma unroll
            for (int k = NSTEP - 1; k >= NHARM; --k) {
                const float ec = pc[k], es = ps[k];
                const float px = ec * x0 - es * y0, py = ec * y0 + es * x0;
                const float qx = ec * x1 + es * y1, qy = ec * y1 - es * x1;
                x0 = c * px - s * qy;  y0 = c * py + s * qx;
                x1 = c * qx - s * py;  y1 = c * qy + s * px;
            }
            rh[i*4+0] = x0; rh[i*4+1] = y0; rh[i*4+2] = x1; rh[i*4+3] = y1;
        }
    }
    __syncthreads();

    if (t < 64) {
        // P00 = r0*v0 + r1*v1 (complex), then Re(e^{i phi0} * P00)
        const float r0x = lh[t*4], r0y = lh[t*4+1], r1x = lh[t*4+2], r1y = lh[t*4+3];
        const float v0x = rh[t*4], v0y = rh[t*4+1], v1x = rh[t*4+2], v1y = rh[t*4+3];
        const float Px = r0x*v0x - r0y*v0y + r1x*v1x - r1y*v1y;
        const float Py = r0x*v0y + r0y*v0x + r1x*v1y + r1y*v1x;
        gs[t] = s0cs[0] * Px - s0cs[1] * Py;
    }
    __syncthreads();

    // ---- exact 64-pt DFT: cos(pi*m/32) = tab[(m+16)&63] ----
    if (t <= NHARM) {
        float a0 = 0.f, a1 = 0.f, a2s = 0.f, a3 = 0.f;
        #pragma unroll
        for (int k = 0; k < NSAMP; k += 4) {
            a0  = fmaf(gs[k+0], tab[(t*(k+0) + 16) & 63], a0);
            a1  = fmaf(gs[k+1], tab[(t*(k+1) + 16) & 63], a1);
            a2s = fmaf(gs[k+2], tab[(t*(k+2) + 16) & 63], a2s);
            a3  = fmaf(gs[k+3], tab[(t*(k+3) + 16) & 63], a3);
        }
        sAB[t].x = ((a0 + a1) + (a2s + a3)) *
                   ((t == 0) ? (1.0f / 64.0f) : (2.0f / 64.0f));
        if (t == 0) sAB[0].y = 0.0f;   // B_0 unused
    } else if (t >= 32 && t <= 31 + NHARM) {
        const int j = t - 31;
        float a0 = 0.f, a1 = 0.f, a2s = 0.f, a3 = 0.f;
        #pragma unroll
        for (int k = 0; k < NSAMP; k += 4) {
            a0  = fmaf(gs[k+0], tab[(j*(k+0)) & 63], a0);
            a1  = fmaf(gs[k+1], tab[(j*(k+1)) & 63], a1);
            a2s = fmaf(gs[k+2], tab[(j*(k+2)) & 63], a2s);
            a3  = fmaf(gs[k+3], tab[(j*(k+3)) & 63], a3);
        }
        sAB[j].y = ((a0 + a1) + (a2s + a3)) * (2.0f / 64.0f);
    }
    __syncthreads();

    // ---- table build: thread t evaluates g at grid point t (scalar) ----
    {
        // u = 2*theta_t = pi * t / 512
        float su, cu;
        sincospif((float)t * (1.0f / 512.0f), &su, &cu);
        const float tw = 2.0f * cu;

        float b1 = 0.f, b2 = 0.f, d1 = 0.f, d2 = 0.f;

        // 3-deep rolling prefetch of (A_k,B_k) via LDS.64.
        // Invariant: at iteration k, f0 == sAB[k]; loads run sAB[24]..sAB[0]
        // (guard k >= 3), so after the loop f0 == sAB[0].
        float2 f0 = sAB[NHARM];
        float2 f1 = sAB[NHARM - 1];
        float2 f2 = sAB[NHARM - 2];

        #pragma unroll
        for (int k = NHARM; k >= 1; --k) {
            const float Ak = f0.x, Bk = f0.y;
            f0 = f1; f1 = f2;
            if (k >= 3) f2 = sAB[k - 3];

            float nb;
            nb = fmaf(tw, b1, Ak - b2); b2 = b1; b1 = nb;
            nb = fmaf(tw, d1, Bk - d2); d2 = d1; d1 = nb;
        }

        float gv = f0.x - b2;              // A0 - b2  (f0 == sAB[0])
        gv = fmaf(cu, b1, gv);
        gv = fmaf(su, d1, gv);
        g[t] = gv;
    }
    __syncthreads();

    // ---- stencil table: t4[t] = (g[t-1], g[t], g[t+1], g[t+2]) ----
    t4[t] = make_float4(g[(t + TSIZE - 1) & (TSIZE - 1)],
                        g[t],
                        g[(t + 1) & (TSIZE - 1)],
                        g[(t + 2) & (TSIZE - 1)]);
    __syncthreads();

    // ---- evaluation: range-reduce + cubic Lagrange ----
    if (!act) return;

    const float SCALE = (float)TSIZE / 3.14159265358979323846f;
    float th[4] = {xv.x, xv.y, xv.z, xv.w};
    float res[4];
    #pragma unroll
    for (int e = 0; e < 4; ++e) {
        const float u  = th[e] * SCALE;
        const float fl = floorf(u);
        const float f  = u - fl;
        const int idx  = ((int)fl) & (TSIZE - 1);
        const float4 p = t4[idx];
        const float fm1 = f - 1.0f, fm2 = f - 2.0f, fp1 = f + 1.0f;
        const float w0 = -f * fm1 * fm2 * (1.0f / 6.0f);
        const float w1 =  fp1 * fm1 * fm2 * 0.5f;
        const float w2 = -fp1 * f * fm2 * 0.5f;
        const float w3 =  fp1 * f * fm1 * (1.0f / 6.0f);
        res[e] = fmaf(w0, p.x, fmaf(w1, p.y, fmaf(w2, p.z, w3 * p.w)));
    }

    out4[T] = make_float4(fmaf(av.x, res[0], bb), fmaf(av.y, res[1], bb),
                          fmaf(av.z, res[2], bb), fmaf(av.w, res[3], bb));
}

// ---------------------------------------------------------------------------
// Fallback for unexpected shapes (direct chain evaluation).
// ---------------------------------------------------------------------------
__global__ void __launch_bounds__(256)
qsp_generic(const float* __restrict__ x,
            const float* __restrict__ phis,
            const float* __restrict__ alphas,
            const float* __restrict__ bias,
            float* __restrict__ out,
            int n, int nsteps)
{
    __shared__ float pc[256], ps[256];
    __shared__ float s0c, s0s;
    int t = threadIdx.x;
    if (t < nsteps && t < 256) {
        float sp, cp; sincosf(phis[t + 1], &sp, &cp);
        pc[t] = cp; ps[t] = sp;
    }
    if (t == 0) {
        float sp, cp; sincosf(phis[0], &sp, &cp);
        s0c = cp; s0s = sp;
    }
    __syncthreads();

    const int i = blockIdx.x * blockDim.x + t;
    if (i >= n) return;

    float s, c; sincosf(x[i], &s, &c);
    float x0 = 1.0f, y0 = 0.0f, x1 = 0.0f, y1 = 0.0f;
    for (int k = 0; k < nsteps; ++k) {
        const float ec = (k < 256) ? pc[k] : cosf(phis[k + 1]);
        const float es = (k < 256) ? ps[k] : sinf(phis[k + 1]);
        const float ux = c * x0 - s * y1;
        const float uy = c * y0 + s * x1;
        const float vx = c * x1 - s * y0;
        const float vy = c * y1 + s * x0;
        x0 = ec * ux - es * uy;
        y0 = es * ux + ec * uy;
        x1 = ec * vx + es * vy;
        y1 = ec * vy - es * vx;
    }
    const float re = s0c * x0 - s0s * y0;
    out[i] = fmaf(alphas[i], re, bias[0]);
}

extern "C" void kernel_launch(void* const* d_in, const int* in_sizes, int n_in,
                              void* d_out, int out_size)
{
    const float* x      = (const float*)d_in[0];
    const float* phis   = (const float*)d_in[1];
    const float* alphas = (const float*)d_in[2];
    const float* bias   = (const float*)d_in[3];
    float* out = (float*)d_out;

    const int n      = in_sizes[0];
    const int nph    = in_sizes[1];
    const int nsteps = nph - 1;

    if (nsteps == NSTEP && (n & 3) == 0) {
        const int nq      = n >> 2;                   // float4 quads
        const int threads = 1024;
        const int blocks  = (nq + threads - 1) / threads;   // 128 for n=524288
        qsp_fused<<<blocks, threads>>>((const float4*)x, phis,
                                       (const float4*)alphas, bias,
                                       (float4*)out, nq);
    } else {
        const int threads = 256;
        const int blocks  = (n + threads - 1) / threads;
        qsp_generic<<<blocks, threads>>>(x, phis, alphas, bias, out, n, nsteps);
    }
}